// round 8
// baseline (speedup 1.0000x reference)
#include <cuda_runtime.h>
#include <cstdint>
#include <math.h>

#define NEG_F (-3.402823466e+38f)   // jnp.finfo(float32).min == -FLT_MAX
#define NTHREADS 256

// ---------------------------------------------------------------------------
// One block per row i of the N x N mask (N = t*h*w).
// Fast path (w % 8 == 0): each thread emits 8-wide chunks. Per chunk the
// (tj, hj) coords are constant, so a uniform classify rejects ~95% of chunks
// as all -FLT_MAX (immediate v8 store, no barrier, no second pass). The rare
// chunks near the row's mask support evaluate the full predicate per element.
// Fallback path: fill + __syncthreads + scatter (previous champion).
// ---------------------------------------------------------------------------
__global__ void __launch_bounds__(NTHREADS)
fused_mask_kernel(const int* __restrict__ tp, const int* __restrict__ hp,
                  const int* __restrict__ wp, float* __restrict__ out, int N) {
    const int i   = blockIdx.x;
    const int tid = threadIdx.x;
    float* row = out + (size_t)i * (size_t)N;

    const int t = *tp;
    const int h = *hp;
    const int w = *wp;

    // decode row coordinate
    const int wi = i % w;
    const int ri = i / w;
    const int hi = ri % h;
    const int ti = ri / h;

    if ((w & 7) == 0) {
        // ---------------- fast path: classify 8-wide chunks ----------------
        const int nchunk = N >> 3;
        for (int f = tid; f < nchunk; f += NTHREADS) {
            const int j0  = f << 3;
            const int wjc = j0 % w;
            const int rj  = j0 / w;
            const int hj  = rj % h;
            const int tj  = rj / h;

            const int dt = abs(ti - tj);
            const int dh = abs(hi - hj);

            const bool nearWin = (dt <= 2) & (dh <= 2);
            const bool pt = (dt == 1) | (dt == 2) | (dt == 4);
            const bool ph = (dh == 1) | (dh == 2) | (dh == 4);
            const bool axisT = pt & (dh == 0);
            const bool axisH = ph & (dt == 0);

            const int rel = wi - wjc;   // wj = wjc + k, k in [0,8)

            // any column of this chunk possibly masked?
            const bool slow =
                (nearWin && rel >= -4 && rel <= 11) ||
                ((axisT | axisH) && rel >= 0 && rel <= 7);

            float* p = row + j0;
            if (!slow) {
                const float v = NEG_F;
                asm volatile(
                    "st.global.v8.f32 [%0], {%1,%2,%3,%4,%5,%6,%7,%8};"
                    :: "l"(p), "f"(v), "f"(v), "f"(v), "f"(v),
                               "f"(v), "f"(v), "f"(v), "f"(v)
                    : "memory");
            } else {
                float vals[8];
                #pragma unroll
                for (int k = 0; k < 8; k++) {
                    const int dw = abs(rel - k);
                    const bool pw = (dw == 1) | (dw == 2) | (dw == 4);
                    const bool local  = nearWin & (dw <= 2);
                    const bool sparse = (pt & (dh == 0) & (dw == 0))
                                      | (ph & (dt == 0) & (dw == 0))
                                      | (pw & (dt == 0) & (dh == 0));
                    vals[k] = (local | sparse) ? 0.0f : NEG_F;
                }
                asm volatile(
                    "st.global.v8.f32 [%0], {%1,%2,%3,%4,%5,%6,%7,%8};"
                    :: "l"(p),
                       "f"(vals[0]), "f"(vals[1]), "f"(vals[2]), "f"(vals[3]),
                       "f"(vals[4]), "f"(vals[5]), "f"(vals[6]), "f"(vals[7])
                    : "memory");
            }
        }
    } else {
        // ---------------- fallback: fill + barrier + scatter ----------------
        const int n4 = N >> 2;
        float4* row4 = (float4*)row;
        const float4 v = make_float4(NEG_F, NEG_F, NEG_F, NEG_F);
        #pragma unroll 8
        for (int f = tid; f < n4; f += NTHREADS) row4[f] = v;

        __syncthreads();

        if (tid < 131) {
            int dt, dh, dw;
            if (tid < 125) {
                dt = tid / 25 - 2;
                dh = (tid / 5) % 5 - 2;
                dw = tid % 5 - 2;
            } else {
                const int s    = tid - 125;
                const int axis = s >> 1;
                const int off  = (s & 1) ? 4 : -4;
                dt = (axis == 0) ? off : 0;
                dh = (axis == 1) ? off : 0;
                dw = (axis == 2) ? off : 0;
            }
            const int tj = ti + dt;
            const int hj = hi + dh;
            const int wj = wi + dw;
            if ((unsigned)tj < (unsigned)t &&
                (unsigned)hj < (unsigned)h &&
                (unsigned)wj < (unsigned)w) {
                row[(tj * h + hj) * w + wj] = 0.0f;
            }
        }
    }
}

// ---------------------------------------------------------------------------
extern "C" void kernel_launch(void* const* d_in, const int* in_sizes, int n_in,
                              void* d_out, int out_size) {
    const int N = (int)(sqrt((double)out_size) + 0.5);   // out is N*N floats

    const int* tp = (const int*)d_in[0];
    const int* hp = (const int*)d_in[1];
    const int* wp = (const int*)d_in[2];

    fused_mask_kernel<<<N, NTHREADS>>>(tp, hp, wp, (float*)d_out, N);
}

// round 9
// speedup vs baseline: 1.0172x; 1.0172x over previous
#include <cuda_runtime.h>
#include <cstdint>
#include <math.h>

#define NEG_F (-3.402823466e+38f)   // jnp.finfo(float32).min == -FLT_MAX
#define NTHREADS 512                // 2 rows per block
#define ROWS_PER_BLOCK 2

// ---------------------------------------------------------------------------
// Two rows per block (512 threads). Phase 1: coalesced float4 fill of both
// rows (-FLT_MAX). One __syncthreads. Phase 2: threads 0..261 overwrite the
// <=131 masked columns of each row with 0.0f — lines are still dirty in L2
// from phase 1 of this same block, so the zeros merge with no extra DRAM
// traffic. Identical store stream to the 39.4us champion but half the CTAs
// and half the barriers.
// Masked columns per row:
//   - local window: dt,dh,dw in [-2,2]                      -> 125 candidates
//   - sparse pow2 {1,2,4} along exactly one axis (others 0) -> only +/-4 adds
//     new entries (1,2 lie inside the window)               ->   6 candidates
// ---------------------------------------------------------------------------
__global__ void __launch_bounds__(NTHREADS)
fused_mask_kernel(const int* __restrict__ tp, const int* __restrict__ hp,
                  const int* __restrict__ wp, float4* __restrict__ out4, int N) {
    const int tid  = threadIdx.x;
    const int base = blockIdx.x * ROWS_PER_BLOCK;     // first row of this block
    const int n4   = N >> 2;                          // float4s per row

    // ---- Phase 1: fill both rows with -FLT_MAX (coalesced) ----
    float4* blk = out4 + (size_t)base * (size_t)n4;   // 2*n4 float4s
    const int tot4 = ROWS_PER_BLOCK * n4;
    const float4 v = make_float4(NEG_F, NEG_F, NEG_F, NEG_F);
    #pragma unroll 8
    for (int f = tid; f < tot4; f += NTHREADS) blk[f] = v;

    __syncthreads();

    // ---- Phase 2: overwrite masked columns with 0.0f ----
    if (tid < 131 * ROWS_PER_BLOCK) {
        const int t = *tp;
        const int h = *hp;
        const int w = *wp;

        const int rl   = tid / 131;          // 0 or 1: local row
        const int cand = tid - rl * 131;     // candidate index
        const int i    = base + rl;          // global row

        // decode row coordinate
        const int wi = i % w;
        const int ri = i / w;
        const int hi = ri % h;
        const int ti = ri / h;

        int dt, dh, dw;
        if (cand < 125) {
            dt = cand / 25 - 2;
            dh = (cand / 5) % 5 - 2;
            dw = cand % 5 - 2;
        } else {
            const int s    = cand - 125;       // 0..5
            const int axis = s >> 1;           // 0:t 1:h 2:w
            const int off  = (s & 1) ? 4 : -4;
            dt = (axis == 0) ? off : 0;
            dh = (axis == 1) ? off : 0;
            dw = (axis == 2) ? off : 0;
        }

        const int tj = ti + dt;
        const int hj = hi + dh;
        const int wj = wi + dw;
        if ((unsigned)tj < (unsigned)t &&
            (unsigned)hj < (unsigned)h &&
            (unsigned)wj < (unsigned)w) {
            const int j = (tj * h + hj) * w + wj;
            ((float*)(out4 + (size_t)i * (size_t)n4))[j] = 0.0f;
        }
    }
}

// ---------------------------------------------------------------------------
extern "C" void kernel_launch(void* const* d_in, const int* in_sizes, int n_in,
                              void* d_out, int out_size) {
    const int N = (int)(sqrt((double)out_size) + 0.5);   // out is N*N floats

    const int* tp = (const int*)d_in[0];
    const int* hp = (const int*)d_in[1];
    const int* wp = (const int*)d_in[2];

    fused_mask_kernel<<<N / ROWS_PER_BLOCK, NTHREADS>>>(
        tp, hp, wp, (float4*)d_out, N);
}